// round 1
// baseline (speedup 1.0000x reference)
#include <cuda_runtime.h>

// GCN 2-layer:
//   out = A(relu(A(x) @ W1 + b1) @ W2) + b2,  A = sym-normalized adjacency with self-loops.
// Aggregation commutes with the dense linear map, so we always aggregate in 64-dim space.

#define N_NODES 50000
#define N_EDGES 800000
#define DIM_IN 64
#define DIM_HID 128

// Scratch (allocation-free rule: __device__ globals)
__device__ float g_deg [N_NODES];
__device__ float g_dinv[N_NODES];
__device__ float g_t   [N_NODES * DIM_IN];   // A(x)
__device__ float g_h   [N_NODES * DIM_HID];  // relu(t@W1+b1)
__device__ float g_g   [N_NODES * DIM_IN];   // h@W2

// ---------------- degree / norm ----------------
__global__ void k_deg_init(int n) {
    int i = blockIdx.x * blockDim.x + threadIdx.x;
    if (i < n) g_deg[i] = 1.0f;  // self-loop
}

__global__ void k_deg_count(const int* __restrict__ dst, int e) {
    int i = blockIdx.x * blockDim.x + threadIdx.x;
    if (i < e) atomicAdd(&g_deg[dst[i]], 1.0f);
}

__global__ void k_dinv(int n) {
    int i = blockIdx.x * blockDim.x + threadIdx.x;
    if (i < n) g_dinv[i] = rsqrtf(g_deg[i]);
}

// ---------------- self-loop init: out[i][:] = bias + dinv[i]^2 * feat[i][:] ----------------
// 64 floats per node = 16 float4 per node. bias may be null.
__global__ void k_self_init64(const float* __restrict__ feat,
                              const float* __restrict__ bias,
                              float* __restrict__ out, int n) {
    int idx = blockIdx.x * blockDim.x + threadIdx.x;  // n*16 threads
    if (idx >= n * 16) return;
    int i  = idx >> 4;
    int j4 = (idx & 15) << 2;
    float d = g_dinv[i];
    float s = d * d;
    float4 v = reinterpret_cast<const float4*>(feat)[idx];
    float4 o;
    if (bias) {
        o.x = bias[j4 + 0] + s * v.x;
        o.y = bias[j4 + 1] + s * v.y;
        o.z = bias[j4 + 2] + s * v.z;
        o.w = bias[j4 + 3] + s * v.w;
    } else {
        o.x = s * v.x; o.y = s * v.y; o.z = s * v.z; o.w = s * v.w;
    }
    reinterpret_cast<float4*>(out)[idx] = o;
}

// ---------------- edge aggregation (64-dim): out[dst] += norm * feat[src] ----------------
// 16 lanes per edge, one float4 each.
__global__ void k_edge_agg64(const int* __restrict__ src,
                             const int* __restrict__ dst,
                             const float* __restrict__ feat,
                             float* __restrict__ out, int e) {
    long long tid = (long long)blockIdx.x * blockDim.x + threadIdx.x;
    int eidx = (int)(tid >> 4);
    if (eidx >= e) return;
    int lane = (int)(tid & 15);
    int s = src[eidx];
    int d = dst[eidx];
    float norm = g_dinv[s] * g_dinv[d];
    float4 v = reinterpret_cast<const float4*>(feat + (size_t)s * 64)[lane];
    float* o = out + (size_t)d * 64 + lane * 4;
    atomicAdd(o + 0, v.x * norm);
    atomicAdd(o + 1, v.y * norm);
    atomicAdd(o + 2, v.z * norm);
    atomicAdd(o + 3, v.w * norm);
}

// ---------------- GEMM1: h = relu(t @ W1 + b1)   [n,64] x [64,128] ----------------
// Block: (128 cols, 2 row-lanes) = 256 threads. Block covers 16 rows.
// W1 staged once per block in smem (32 KB), conflict-free column access.
__global__ void k_gemm1(const float* __restrict__ A, const float* __restrict__ W,
                        const float* __restrict__ b, float* __restrict__ out, int n) {
    __shared__ float Ws[64 * 128];
    int tid = threadIdx.y * 128 + threadIdx.x;  // 0..255
    for (int i = tid; i < 64 * 128; i += 256) Ws[i] = W[i];
    __syncthreads();

    int j = threadIdx.x;        // column 0..127
    float bj = b[j];
    int row0 = blockIdx.x * 16 + threadIdx.y;
    #pragma unroll 1
    for (int r = row0; r < min(row0 + 16, n) && r < n; r += 2) {
        if (r >= blockIdx.x * 16 + 16) break;
        const float* a = A + (size_t)r * 64;
        float acc = bj;
        #pragma unroll
        for (int k = 0; k < 64; k++) acc = fmaf(a[k], Ws[k * 128 + j], acc);
        out[(size_t)r * 128 + j] = fmaxf(acc, 0.0f);
    }
}

// ---------------- GEMM2: g = h @ W2   [n,128] x [128,64] ----------------
// Block: (64 cols, 4 row-lanes) = 256 threads. Block covers 16 rows.
__global__ void k_gemm2(const float* __restrict__ A, const float* __restrict__ W,
                        float* __restrict__ out, int n) {
    __shared__ float Ws[128 * 64];
    int tid = threadIdx.y * 64 + threadIdx.x;  // 0..255
    for (int i = tid; i < 128 * 64; i += 256) Ws[i] = W[i];
    __syncthreads();

    int j = threadIdx.x;  // column 0..63
    int row0 = blockIdx.x * 16 + threadIdx.y;
    #pragma unroll 1
    for (int r = row0; r < n; r += 4) {
        if (r >= blockIdx.x * 16 + 16) break;
        const float* a = A + (size_t)r * 128;
        float acc = 0.0f;
        #pragma unroll
        for (int k = 0; k < 128; k++) acc = fmaf(a[k], Ws[k * 64 + j], acc);
        out[(size_t)r * 64 + j] = acc;
    }
}

extern "C" void kernel_launch(void* const* d_in, const int* in_sizes, int n_in,
                              void* d_out, int out_size) {
    const float* x  = (const float*)d_in[0];
    const int*   ei = (const int*)  d_in[1];
    const float* W1 = (const float*)d_in[2];
    const float* b1 = (const float*)d_in[3];
    const float* W2 = (const float*)d_in[4];
    const float* b2 = (const float*)d_in[5];
    float* out = (float*)d_out;

    int n = in_sizes[0] / DIM_IN;       // 50000
    int e = in_sizes[1] / 2;            // 800000
    const int* src = ei;
    const int* dst = ei + e;

    float* t = nullptr, *h = nullptr, *g = nullptr;
    cudaGetSymbolAddress((void**)&t, g_t);
    cudaGetSymbolAddress((void**)&h, g_h);
    cudaGetSymbolAddress((void**)&g, g_g);

    const int TB = 256;

    // degree + dinv
    k_deg_init <<<(n + TB - 1) / TB, TB>>>(n);
    k_deg_count<<<(e + TB - 1) / TB, TB>>>(dst, e);
    k_dinv     <<<(n + TB - 1) / TB, TB>>>(n);

    // layer 1: t = A(x)
    k_self_init64<<<(n * 16 + TB - 1) / TB, TB>>>(x, nullptr, t, n);
    {
        long long work = (long long)e * 16;
        k_edge_agg64<<<(int)((work + TB - 1) / TB), TB>>>(src, dst, x, t, e);
    }
    // h = relu(t @ W1 + b1)
    k_gemm1<<<(n + 15) / 16, dim3(128, 2)>>>(t, W1, b1, h, n);

    // layer 2: g = h @ W2
    k_gemm2<<<(n + 15) / 16, dim3(64, 4)>>>(h, W2, g, n);
    // out = A(g) + b2
    k_self_init64<<<(n * 16 + TB - 1) / TB, TB>>>(g, b2, out, n);
    {
        long long work = (long long)e * 16;
        k_edge_agg64<<<(int)((work + TB - 1) / TB), TB>>>(src, dst, g, out, e);
    }
}

// round 2
// speedup vs baseline: 1.8679x; 1.8679x over previous
#include <cuda_runtime.h>

// 2-layer GCN, restructured:
//   A = D^{-1/2} (Adj + I) D^{-1/2}
//   layer1: y = dinv*x; z = (Adj+I)y  [pure gather/scatter]; h = relu((dinv*z)@W1 + b1)
//   layer2: y2 = dinv*(h@W2) [fused epilogue]; z2 = (Adj+I)y2; out = dinv*z2 + b2

#define N_NODES 50000
#define DIM_IN 64
#define DIM_HID 128

__device__ float g_deg [N_NODES];
__device__ float g_dinv[N_NODES];
__device__ float g_y   [N_NODES * DIM_IN];   // dinv * x
__device__ float g_z   [N_NODES * DIM_IN];   // (Adj+I) y
__device__ float g_h   [N_NODES * DIM_HID];  // relu(...)
__device__ float g_y2  [N_NODES * DIM_IN];   // dinv * (h @ W2)

// ---------------- degree / norm ----------------
__global__ void k_deg_init(int n) {
    int i = blockIdx.x * blockDim.x + threadIdx.x;
    if (i < n) g_deg[i] = 1.0f;  // self-loop
}
__global__ void k_deg_count(const int* __restrict__ dst, int e) {
    int i = blockIdx.x * blockDim.x + threadIdx.x;
    if (i < e) atomicAdd(&g_deg[dst[i]], 1.0f);
}
__global__ void k_dinv(int n) {
    int i = blockIdx.x * blockDim.x + threadIdx.x;
    if (i < n) g_dinv[i] = rsqrtf(g_deg[i]);
}

// ---------------- prescale: y = dinv*x, z = y (self-loop init) ----------------
__global__ void k_prescale(const float* __restrict__ x, float* __restrict__ y,
                           float* __restrict__ z, int n) {
    int idx = blockIdx.x * blockDim.x + threadIdx.x;  // n*16
    if (idx >= n * 16) return;
    float d = g_dinv[idx >> 4];
    float4 v = reinterpret_cast<const float4*>(x)[idx];
    float4 o = {d * v.x, d * v.y, d * v.z, d * v.w};
    reinterpret_cast<float4*>(y)[idx] = o;
    reinterpret_cast<float4*>(z)[idx] = o;
}

// ---------------- edge aggregation: z[dst] += y[src]  (pure, 64-dim) ----------------
// 16 lanes per edge, one float4 gather + one v4 red each.
__global__ void k_edge_agg(const int* __restrict__ src, const int* __restrict__ dst,
                           const float* __restrict__ y, float* __restrict__ z, int e) {
    long long tid = (long long)blockIdx.x * blockDim.x + threadIdx.x;
    int eidx = (int)(tid >> 4);
    if (eidx >= e) return;
    int lane = (int)(tid & 15);
    int s = __ldg(src + eidx);
    int d = __ldg(dst + eidx);
    float4 v = reinterpret_cast<const float4*>(y)[s * 16 + lane];
    float* o = z + (size_t)d * 64 + lane * 4;
    asm volatile("red.global.add.v4.f32 [%0], {%1, %2, %3, %4};"
                 :: "l"(o), "f"(v.x), "f"(v.y), "f"(v.z), "f"(v.w) : "memory");
}

// ---------------- GEMM1: h = relu(b1 + dinv[r] * (z_row @ W1))  [n,64]x[64,128] ----------------
// block (32,8): thread = (row, 4 cols). W1 in smem, LDS.128 conflict-free.
__global__ void k_gemm1(const float* __restrict__ Z, const float* __restrict__ W,
                        const float* __restrict__ b, float* __restrict__ H, int n) {
    __shared__ float Ws[64 * 128];
    int tid = threadIdx.y * 32 + threadIdx.x;
    {
        const float4* w4 = reinterpret_cast<const float4*>(W);
        float4* s4 = reinterpret_cast<float4*>(Ws);
        for (int i = tid; i < 64 * 128 / 4; i += 256) s4[i] = w4[i];
    }
    __syncthreads();
    int r = blockIdx.x * 8 + threadIdx.y;
    if (r >= n) return;
    int tx = threadIdx.x;
    const float4* a4 = reinterpret_cast<const float4*>(Z + (size_t)r * 64);
    const float4* ws4 = reinterpret_cast<const float4*>(Ws);
    float4 acc = {0.f, 0.f, 0.f, 0.f};
    #pragma unroll
    for (int k4 = 0; k4 < 16; k4++) {
        float4 av = a4[k4];  // broadcast within warp
        float4 w;
        w = ws4[(4 * k4 + 0) * 32 + tx];
        acc.x = fmaf(av.x, w.x, acc.x); acc.y = fmaf(av.x, w.y, acc.y);
        acc.z = fmaf(av.x, w.z, acc.z); acc.w = fmaf(av.x, w.w, acc.w);
        w = ws4[(4 * k4 + 1) * 32 + tx];
        acc.x = fmaf(av.y, w.x, acc.x); acc.y = fmaf(av.y, w.y, acc.y);
        acc.z = fmaf(av.y, w.z, acc.z); acc.w = fmaf(av.y, w.w, acc.w);
        w = ws4[(4 * k4 + 2) * 32 + tx];
        acc.x = fmaf(av.z, w.x, acc.x); acc.y = fmaf(av.z, w.y, acc.y);
        acc.z = fmaf(av.z, w.z, acc.z); acc.w = fmaf(av.z, w.w, acc.w);
        w = ws4[(4 * k4 + 3) * 32 + tx];
        acc.x = fmaf(av.w, w.x, acc.x); acc.y = fmaf(av.w, w.y, acc.y);
        acc.z = fmaf(av.w, w.z, acc.z); acc.w = fmaf(av.w, w.w, acc.w);
    }
    float s = g_dinv[r];
    float4 bb = reinterpret_cast<const float4*>(b)[tx];
    float4 o;
    o.x = fmaxf(fmaf(s, acc.x, bb.x), 0.f);
    o.y = fmaxf(fmaf(s, acc.y, bb.y), 0.f);
    o.z = fmaxf(fmaf(s, acc.z, bb.z), 0.f);
    o.w = fmaxf(fmaf(s, acc.w, bb.w), 0.f);
    reinterpret_cast<float4*>(H + (size_t)r * 128)[tx] = o;
}

// ---------------- GEMM2: y2 = dinv[r] * (h_row @ W2); also z2-init into out ----------------
// block (16,16): thread = (row, 4 cols of 64). [n,128]x[128,64]
__global__ void k_gemm2(const float* __restrict__ H, const float* __restrict__ W,
                        float* __restrict__ Y2, float* __restrict__ Out, int n) {
    __shared__ float Ws[128 * 64];
    int tid = threadIdx.y * 16 + threadIdx.x;
    {
        const float4* w4 = reinterpret_cast<const float4*>(W);
        float4* s4 = reinterpret_cast<float4*>(Ws);
        for (int i = tid; i < 128 * 64 / 4; i += 256) s4[i] = w4[i];
    }
    __syncthreads();
    int r = blockIdx.x * 16 + threadIdx.y;
    if (r >= n) return;
    int tx = threadIdx.x;
    const float4* a4 = reinterpret_cast<const float4*>(H + (size_t)r * 128);
    const float4* ws4 = reinterpret_cast<const float4*>(Ws);
    float4 acc = {0.f, 0.f, 0.f, 0.f};
    #pragma unroll
    for (int k4 = 0; k4 < 32; k4++) {
        float4 av = a4[k4];
        float4 w;
        w = ws4[(4 * k4 + 0) * 16 + tx];
        acc.x = fmaf(av.x, w.x, acc.x); acc.y = fmaf(av.x, w.y, acc.y);
        acc.z = fmaf(av.x, w.z, acc.z); acc.w = fmaf(av.x, w.w, acc.w);
        w = ws4[(4 * k4 + 1) * 16 + tx];
        acc.x = fmaf(av.y, w.x, acc.x); acc.y = fmaf(av.y, w.y, acc.y);
        acc.z = fmaf(av.y, w.z, acc.z); acc.w = fmaf(av.y, w.w, acc.w);
        w = ws4[(4 * k4 + 2) * 16 + tx];
        acc.x = fmaf(av.z, w.x, acc.x); acc.y = fmaf(av.z, w.y, acc.y);
        acc.z = fmaf(av.z, w.z, acc.z); acc.w = fmaf(av.z, w.w, acc.w);
        w = ws4[(4 * k4 + 3) * 16 + tx];
        acc.x = fmaf(av.w, w.x, acc.x); acc.y = fmaf(av.w, w.y, acc.y);
        acc.z = fmaf(av.w, w.z, acc.z); acc.w = fmaf(av.w, w.w, acc.w);
    }
    float s = g_dinv[r];
    float4 o = {s * acc.x, s * acc.y, s * acc.z, s * acc.w};
    reinterpret_cast<float4*>(Y2 + (size_t)r * 64)[tx] = o;
    reinterpret_cast<float4*>(Out + (size_t)r * 64)[tx] = o;  // self-loop init
}

// ---------------- finish: out = dinv * z2 + b2 (in place) ----------------
__global__ void k_finish(float* __restrict__ out, const float* __restrict__ b2, int n) {
    int idx = blockIdx.x * blockDim.x + threadIdx.x;  // n*16
    if (idx >= n * 16) return;
    float d = g_dinv[idx >> 4];
    int j4 = idx & 15;
    float4 v = reinterpret_cast<float4*>(out)[idx];
    float4 bb = reinterpret_cast<const float4*>(b2)[j4];
    float4 o;
    o.x = fmaf(d, v.x, bb.x);
    o.y = fmaf(d, v.y, bb.y);
    o.z = fmaf(d, v.z, bb.z);
    o.w = fmaf(d, v.w, bb.w);
    reinterpret_cast<float4*>(out)[idx] = o;
}

extern "C" void kernel_launch(void* const* d_in, const int* in_sizes, int n_in,
                              void* d_out, int out_size) {
    const float* x  = (const float*)d_in[0];
    const int*   ei = (const int*)  d_in[1];
    const float* W1 = (const float*)d_in[2];
    const float* b1 = (const float*)d_in[3];
    const float* W2 = (const float*)d_in[4];
    const float* b2 = (const float*)d_in[5];
    float* out = (float*)d_out;

    int n = in_sizes[0] / DIM_IN;   // 50000
    int e = in_sizes[1] / 2;        // 800000
    const int* src = ei;
    const int* dst = ei + e;

    float *y, *z, *h, *y2;
    cudaGetSymbolAddress((void**)&y,  g_y);
    cudaGetSymbolAddress((void**)&z,  g_z);
    cudaGetSymbolAddress((void**)&h,  g_h);
    cudaGetSymbolAddress((void**)&y2, g_y2);

    const int TB = 256;
    long long ew = (long long)e * 16;

    // degree + dinv
    k_deg_init <<<(n + TB - 1) / TB, TB>>>(n);
    k_deg_count<<<(e + TB - 1) / TB, TB>>>(dst, e);
    k_dinv     <<<(n + TB - 1) / TB, TB>>>(n);

    // layer 1
    k_prescale<<<(n * 16 + TB - 1) / TB, TB>>>(x, y, z, n);
    k_edge_agg<<<(int)((ew + TB - 1) / TB), TB>>>(src, dst, y, z, e);
    k_gemm1<<<(n + 7) / 8, dim3(32, 8)>>>(z, W1, b1, h, n);

    // layer 2
    k_gemm2<<<(n + 15) / 16, dim3(16, 16)>>>(h, W2, y2, out, n);
    k_edge_agg<<<(int)((ew + TB - 1) / TB), TB>>>(src, dst, y2, out, e);
    k_finish<<<(n * 16 + TB - 1) / TB, TB>>>(out, b2, n);
}